// round 13
// baseline (speedup 1.0000x reference)
#include <cuda_runtime.h>
#include <cuda_fp16.h>
#include <cstdint>

// ---------------------------------------------------------------------------
// Problem constants
// ---------------------------------------------------------------------------
#define NT_TOKENS 16384
#define D_DIM     2048
#define F_DIM     2048
#define NE        4
#define VOCAB_SZ  100000
#define TPE       (VOCAB_SZ / NE)

#define BM        128
#define PADTOT    (NT_TOKENS + NE * BM)   // 16896
#define MT_MAX    (PADTOT / BM)           // 132
#define KTILES    32                      // 2048 / 64 fp16
#define WD_BLOCKS (MT_MAX * NE)           // 528 Wd-cvt blocks

// ---------------------------------------------------------------------------
// Device scratch (allocation-free rule: __device__ globals)
// ---------------------------------------------------------------------------
__device__ int    g_count[NE];
__device__ int    g_perm[PADTOT];
__device__ int    g_done[NE * MT_MAX];    // producers finished per (e,my)
__device__ int    g_wd;                   // Wd-cvt blocks finished
__device__ __half hX [(size_t)NT_TOKENS * D_DIM];
__device__ __half hWg[(size_t)NE * F_DIM * D_DIM];
__device__ __half hWu[(size_t)NE * F_DIM * D_DIM];
__device__ __half hWd[(size_t)NE * D_DIM * F_DIM];
__device__ __half hH [(size_t)PADTOT * F_DIM];

// ---------------------------------------------------------------------------
// Helpers
// ---------------------------------------------------------------------------
__device__ __forceinline__ int expert_of_i32(int t) {
    if (t < 0) t = 0;
    if (t > VOCAB_SZ - 1) t = VOCAB_SZ - 1;
    int e = t / TPE;
    return e > NE - 1 ? NE - 1 : e;
}

// Per-block dtype detect: token_ids declared int64 but may physically be
// int32 (JAX x64 disabled). If int64 (ids < 2^31), every high word is 0.
// Requires blockDim.x == 256.
__device__ __forceinline__ int detect_shift(const int* __restrict__ tok32,
                                            int* smem_flag) {
    if (threadIdx.x == 0) *smem_flag = 0;
    __syncthreads();
    if (tok32[2 * threadIdx.x + 1] != 0) *smem_flag = 1;
    __syncthreads();
    return *smem_flag ? 0 : 1;
}

__device__ __forceinline__ int ld_cg(const int* p) {
    int v;
    asm volatile("ld.global.cg.b32 %0, [%1];" : "=r"(v) : "l"(p));
    return v;
}

// ---------------------------------------------------------------------------
// Kernel 1: fp32->fp16 conversion of X, Wg, Wu  +  routing fused as ONE block.
// grid = (16384, 3):
//   y=0            : X
//   y=1, x<8192    : Wg
//   y=1, x==8192   : routing block (count -> scan -> perm) + flag zeroing
//   y=2, x<8192    : Wu
// ---------------------------------------------------------------------------
__global__ void k_cvt_route(const float* __restrict__ X, const float* __restrict__ Wg,
                            const float* __restrict__ Wu, const int* __restrict__ tok32) {
    const int nW = NE * F_DIM * D_DIM;

    if (blockIdx.y == 1 && blockIdx.x == 8192) {
        // ---- routing + dependency-flag reset: single block, 256 threads ----
        __shared__ int flag;
        __shared__ int hist[NE], fill[NE], poff[NE];
        const int shift = detect_shift(tok32, &flag);
        const int tid = threadIdx.x;
        if (tid < NE) { hist[tid] = 0; fill[tid] = 0; }
        for (int k = tid; k < NE * MT_MAX; k += 256) g_done[k] = 0;
        if (tid == 0) g_wd = 0;
        __syncthreads();
        for (int k = tid; k < NT_TOKENS; k += 256)
            atomicAdd(&hist[expert_of_i32(tok32[(size_t)k << shift])], 1);
        __syncthreads();
        if (tid == 0) {
            int acc = 0;
#pragma unroll
            for (int e = 0; e < NE; ++e) {
                poff[e] = acc;
                g_count[e] = hist[e];
                acc += (hist[e] + BM - 1) / BM * BM;
            }
        }
        __syncthreads();
        for (int k = tid; k < NT_TOKENS; k += 256) {
            int e = expert_of_i32(tok32[(size_t)k << shift]);
            g_perm[poff[e] + atomicAdd(&fill[e], 1)] = k;
        }
        return;
    }

    const float* src;
    __half* dst;
    int n;
    switch (blockIdx.y) {
        case 0:  src = X;  dst = hX;  n = NT_TOKENS * D_DIM; break;
        case 1:  src = Wg; dst = hWg; n = nW; break;
        default: src = Wu; dst = hWu; n = nW; break;
    }
    int i = (blockIdx.x * blockDim.x + threadIdx.x) * 8;
    if (i < n) {
        float4 f0 = *(const float4*)(src + i);
        float4 f1 = *(const float4*)(src + i + 4);
        __half2 h[4];
        h[0] = __floats2half2_rn(f0.x, f0.y);
        h[1] = __floats2half2_rn(f0.z, f0.w);
        h[2] = __floats2half2_rn(f1.x, f1.y);
        h[3] = __floats2half2_rn(f1.z, f1.w);
        *(uint4*)(dst + i) = *(uint4*)h;
    }
}

// ---------------------------------------------------------------------------
// PTX helpers (sm_100-baseline legal)
// ---------------------------------------------------------------------------
__device__ __forceinline__ void cpa16(uint32_t s, const void* g) {
    asm volatile("cp.async.cg.shared.global [%0], [%1], 16;" :: "r"(s), "l"(g));
}
__device__ __forceinline__ void cpa_commit() {
    asm volatile("cp.async.commit_group;");
}
template <int N> __device__ __forceinline__ void cpa_wait() {
    asm volatile("cp.async.wait_group %0;" :: "n"(N) : "memory");
}
__device__ __forceinline__ void ldm_x4(uint32_t* r, uint32_t addr) {
    asm volatile("ldmatrix.sync.aligned.m8n8.x4.shared.b16 {%0,%1,%2,%3}, [%4];"
                 : "=r"(r[0]), "=r"(r[1]), "=r"(r[2]), "=r"(r[3]) : "r"(addr));
}
__device__ __forceinline__ void mma16816(float* c, const uint32_t* a,
                                         uint32_t b0, uint32_t b1) {
    asm volatile(
        "mma.sync.aligned.m16n8k16.row.col.f32.f16.f16.f32 "
        "{%0,%1,%2,%3}, {%4,%5,%6,%7}, {%8,%9}, {%0,%1,%2,%3};"
        : "+f"(c[0]), "+f"(c[1]), "+f"(c[2]), "+f"(c[3])
        : "r"(a[0]), "r"(a[1]), "r"(a[2]), "r"(a[3]), "r"(b0), "r"(b1));
}

// ---------------------------------------------------------------------------
// Shared GEMM body.
// MODE 0 (producer, gate+up): CTA tile 128x64, hH = silu(g)*u; signals g_done.
// MODE 1 (consumer, down+scatter): CTA tile 128x128; spins on g_done/g_wd
//   before its first cp.async, then scatters fp32 rows to out[token].
// Both: BK=64 fp16, 3-stage cp.async ring (32KB/stage), SW128 XOR swizzle,
// one __syncthreads per k-tile, XOR-folded ldmatrix addressing, prefetch
// issued between ks=0 and ks=1.
// ---------------------------------------------------------------------------
template <int MODE>
__device__ __forceinline__ void gemm_body(int e, int my, int n0,
                                          float* __restrict__ out) {
    constexpr int BN = (MODE == 0) ? 64 : 128;
    const int cnt = g_count[e];
    if (my * BM >= cnt) return;

    int base = 0;
#pragma unroll
    for (int k = 0; k < NE; ++k)
        if (k < e) base += (g_count[k] + BM - 1) / BM * BM;
    const int rowstart = base + my * BM;

    constexpr int STAGE = 32768;   // MODE0: A16K+Bg8K+Bu8K ; MODE1: A16K+B16K

    extern __shared__ __align__(16) char smem[];
    const uint32_t su = (uint32_t)__cvta_generic_to_shared(smem);

    const int tid = threadIdx.x;
    const int l   = tid & 31;
    const int wid = tid >> 5;
    const int wm  = (wid & 3) * 32;
    const int wn  = (wid >> 2) * (BN / 2);

    // Consumer gate: wait for Wd conversion + this group's 32 producers.
    // Producers all have lower bids (z slowest dim) -> they always get slots
    // and finish -> no deadlock; worst case this CTA idles in its slot.
    if (MODE == 1) {
        if (tid == 0) {
            const int* wdp = &g_wd;
            const int* gdp = &g_done[e * MT_MAX + my];
            while (ld_cg(wdp) < WD_BLOCKS) __nanosleep(200);
            while (ld_cg(gdp) < 32) __nanosleep(200);
        }
        __syncthreads();
        __threadfence();
    }

    const int c = tid & 7;
    const char* const baseA = (MODE == 0) ? (const char*)hX : (const char*)hH;
    const char* const baseB1 = (MODE == 0) ? (const char*)hWg : (const char*)hWd;
    const char* const baseB2 = (const char*)hWu;       // MODE0 only

    uint32_t aOff[4];
    uint32_t bOff[4];                                  // MODE0 uses [0..1]
    uint32_t dstA[4];
#pragma unroll
    for (int t = 0; t < 4; ++t) {
        const int row = (tid >> 3) + t * 32;
        dstA[t] = (uint32_t)(row * 128 + ((c ^ (row & 7)) * 16));
        if (MODE == 0) {
            const int grow = (my * BM + row) < cnt ? g_perm[rowstart + row] : 0;
            aOff[t] = (uint32_t)grow * (D_DIM * 2) + c * 16;
        } else {
            aOff[t] = (uint32_t)(rowstart + row) * (F_DIM * 2) + c * 16;
        }
    }
    constexpr int NBCHUNK = (MODE == 0) ? 2 : 4;
#pragma unroll
    for (int t = 0; t < NBCHUNK; ++t) {
        const int row = (tid >> 3) + t * 32;
        bOff[t] = (uint32_t)((size_t)e * F_DIM * D_DIM * 2) +
                  (uint32_t)(n0 + row) * (D_DIM * 2) + c * 16;
    }

#define LOADST(slot, kt)                                                     \
    do {                                                                     \
        const uint32_t sb = su + (uint32_t)(slot) * STAGE;                   \
        const uint32_t ko = (uint32_t)(kt) * 128;                            \
        _Pragma("unroll")                                                    \
        for (int t = 0; t < 4; ++t) cpa16(sb + dstA[t], baseA + aOff[t] + ko);\
        _Pragma("unroll")                                                    \
        for (int t = 0; t < NBCHUNK; ++t) {                                  \
            cpa16(sb + 16384 + dstA[t], baseB1 + bOff[t] + ko);              \
            if (MODE == 0) cpa16(sb + 24576 + dstA[t], baseB2 + bOff[t] + ko);\
        }                                                                    \
        cpa_commit();                                                        \
    } while (0)

    // ---- precomputed ldmatrix fragment constants ----
    const int kha = (l >> 4) & 1;
    const int khb = (l >> 3) & 1;
    uint32_t pA[2];
#pragma unroll
    for (int mi = 0; mi < 2; ++mi) {
        const int r = wm + mi * 16 + (l & 15);
        pA[mi] = (uint32_t)(r * 128 + ((kha ^ (r & 7)) << 4));
    }
    constexpr int NBF = BN / 32;
    uint32_t pB[NBF];
#pragma unroll
    for (int bi = 0; bi < NBF; ++bi) {
        const int r = wn + bi * 16 + ((l & 16) ? 8 : 0) + (l & 7);
        pB[bi] = (uint32_t)(16384 + r * 128 + ((khb ^ (r & 7)) << 4));
    }

    // ---- accumulators ----
    constexpr int NT = BN / 16;
    float c1[2][NT][4];
    float c2[2][NT][4];                                // MODE0 only
#pragma unroll
    for (int mi = 0; mi < 2; ++mi)
#pragma unroll
        for (int nt = 0; nt < NT; ++nt)
#pragma unroll
            for (int k = 0; k < 4; ++k) { c1[mi][nt][k] = 0.f; if (MODE == 0) c2[mi][nt][k] = 0.f; }

    LOADST(0, 0);
    LOADST(1, 1);

#define KSTEP(ks)                                                            \
    do {                                                                     \
        const uint32_t kx = (uint32_t)((ks) << 5);                           \
        uint32_t a[2][4];                                                    \
        _Pragma("unroll")                                                    \
        for (int mi = 0; mi < 2; ++mi) ldm_x4(a[mi], sbase + (pA[mi] ^ kx)); \
        uint32_t b1[NBF][4];                                                 \
        _Pragma("unroll")                                                    \
        for (int bi = 0; bi < NBF; ++bi) ldm_x4(b1[bi], sbase + (pB[bi] ^ kx));\
        _Pragma("unroll")                                                    \
        for (int mi = 0; mi < 2; ++mi)                                       \
            _Pragma("unroll")                                                \
            for (int nt = 0; nt < NT; ++nt)                                  \
                mma16816(c1[mi][nt], a[mi], b1[nt >> 1][(nt & 1) * 2],       \
                         b1[nt >> 1][(nt & 1) * 2 + 1]);                     \
        if (MODE == 0) {                                                     \
            uint32_t b2[NBF][4];                                             \
            _Pragma("unroll")                                                \
            for (int bi = 0; bi < NBF; ++bi)                                 \
                ldm_x4(b2[bi], sbase + 8192 + (pB[bi] ^ kx));                \
            _Pragma("unroll")                                                \
            for (int mi = 0; mi < 2; ++mi)                                   \
                _Pragma("unroll")                                            \
                for (int nt = 0; nt < NT; ++nt)                              \
                    mma16816(c2[mi][nt], a[mi], b2[nt >> 1][(nt & 1) * 2],   \
                             b2[nt >> 1][(nt & 1) * 2 + 1]);                 \
        }                                                                    \
    } while (0)

    // Single-sync ring: LOADST(kt+2) writes slot (kt-1)%3 whose readers all
    // finished before this iteration's barrier; reads of slot kt%3 are
    // published block-wide by the same barrier.
    for (int kt = 0; kt < KTILES; ++kt) {
        if (kt == KTILES - 1) cpa_wait<0>(); else cpa_wait<1>();
        __syncthreads();
        const uint32_t sbase = su + (uint32_t)(kt % 3) * STAGE;

        KSTEP(0);
        if (kt + 2 < KTILES) LOADST((kt + 2) % 3, kt + 2);
        KSTEP(1);
        KSTEP(2);
        KSTEP(3);
    }
#undef KSTEP
#undef LOADST

    // ---- epilogue ----
    const int g   = l >> 2;
    const int tig = l & 3;
    const int colbase = n0 + wn + tig * 2;

#pragma unroll
    for (int mi = 0; mi < 2; ++mi) {
#pragma unroll
        for (int h = 0; h < 2; ++h) {
            const int row_local = wm + mi * 16 + h * 8 + g;
            const int p = rowstart + row_local;
            if (MODE == 0) {
                __half* dst = hH + (size_t)p * F_DIM + colbase;
#pragma unroll
                for (int nt = 0; nt < NT; ++nt) {
                    float gv0 = c1[mi][nt][h * 2],     uv0 = c2[mi][nt][h * 2];
                    float gv1 = c1[mi][nt][h * 2 + 1], uv1 = c2[mi][nt][h * 2 + 1];
                    float v0 = (gv0 / (1.0f + __expf(-gv0))) * uv0;
                    float v1 = (gv1 / (1.0f + __expf(-gv1))) * uv1;
                    *(__half2*)(dst + nt * 8) = __floats2half2_rn(v0, v1);
                }
            } else {
                if ((my * BM + row_local) < cnt) {
                    const int tok = g_perm[p];
                    float* dst = out + (size_t)tok * D_DIM + colbase;
#pragma unroll
                    for (int nt = 0; nt < NT; ++nt)
                        *(float2*)(dst + nt * 8) =
                            make_float2(c1[mi][nt][h * 2], c1[mi][nt][h * 2 + 1]);
                }
            }
        }
    }

    // Producer signal: every thread fences its stores, then one arrival.
    if (MODE == 0) {
        __threadfence();
        __syncthreads();
        if (tid == 0) atomicAdd(&g_done[e * MT_MAX + my], 1);
    }
}

// ---------------------------------------------------------------------------
// Fused GEMM kernel.  grid = (33, 132, 6):
//   z<4, x<32  : producer (gate+up), e=z, my=y, n0=x*64
//   z<4, x==32 : Wd fp32->fp16 cvt blocks (528), signal g_wd
//   z>=4       : consumer (down+scatter), linearized -> (e, my, nb)
// All producer bids precede all consumer bids (z is slowest dim).
// ---------------------------------------------------------------------------
__global__ __launch_bounds__(256, 2)
void k_fused(float* __restrict__ out, const float* __restrict__ Wd32) {
    if (blockIdx.z < NE) {
        if (blockIdx.x == F_DIM / 64) {
            // ---- Wd fp32->fp16 conversion (528 blocks, grid-stride) ----
            const int bid = blockIdx.y * NE + blockIdx.z;
            const size_t stride = (size_t)WD_BLOCKS * 256 * 8;
            for (size_t i = ((size_t)bid * 256 + threadIdx.x) * 8;
                 i < (size_t)NE * D_DIM * F_DIM; i += stride) {
                float4 f0 = *(const float4*)(Wd32 + i);
                float4 f1 = *(const float4*)(Wd32 + i + 4);
                __half2 h[4];
                h[0] = __floats2half2_rn(f0.x, f0.y);
                h[1] = __floats2half2_rn(f0.z, f0.w);
                h[2] = __floats2half2_rn(f1.x, f1.y);
                h[3] = __floats2half2_rn(f1.z, f1.w);
                *(uint4*)(hWd + i) = *(uint4*)h;
            }
            __threadfence();
            __syncthreads();
            if (threadIdx.x == 0) atomicAdd(&g_wd, 1);
            return;
        }
        gemm_body<0>(blockIdx.z, blockIdx.y, blockIdx.x * 64, nullptr);
    } else {
        const int cid = (blockIdx.z - NE) * (33 * MT_MAX) +
                        blockIdx.y * 33 + blockIdx.x;
        if (cid >= NE * MT_MAX * (D_DIM / 128)) return;
        const int e   = cid / (MT_MAX * 16);
        const int rem = cid % (MT_MAX * 16);
        gemm_body<1>(e, rem / 16, (rem % 16) * 128, out);
    }
}

// ---------------------------------------------------------------------------
// Entry.  2 launches: cvt+route, fused GEMM (producers + Wd cvt + consumers).
// ---------------------------------------------------------------------------
extern "C" void kernel_launch(void* const* d_in, const int* in_sizes, int n_in,
                              void* d_out, int out_size) {
    const float* X     = (const float*)d_in[0];
    const int*   tok32 = (const int*)d_in[1];
    const float* Wg    = (const float*)d_in[2];
    const float* Wu    = (const float*)d_in[3];
    const float* Wd    = (const float*)d_in[4];
    float*       out   = (float*)d_out;

    static bool attr_done = false;
    if (!attr_done) {
        cudaFuncSetAttribute(k_fused, cudaFuncAttributeMaxDynamicSharedMemorySize, 3 * 32768);
        attr_done = true;
    }

    // 1: conversion of X/Wg/Wu + fused routing block (+flag reset)
    dim3 gcvt(NT_TOKENS * D_DIM / (256 * 8), 3);   // (16384, 3)
    k_cvt_route<<<gcvt, 256>>>(X, Wg, Wu, tok32);

    // 2: fused producers + Wd cvt + consumers
    dim3 grid(F_DIM / 64 + 1, MT_MAX, NE + 2);     // (33, 132, 6)
    k_fused<<<grid, 256, 3 * 32768>>>(out, Wd);
}

// round 14
// speedup vs baseline: 1.0039x; 1.0039x over previous
#include <cuda_runtime.h>
#include <cuda_fp16.h>
#include <cstdint>

// ---------------------------------------------------------------------------
// Problem constants
// ---------------------------------------------------------------------------
#define NT_TOKENS 16384
#define D_DIM     2048
#define F_DIM     2048
#define NE        4
#define VOCAB_SZ  100000
#define TPE       (VOCAB_SZ / NE)

#define BM        128
#define PADTOT    (NT_TOKENS + NE * BM)   // 16896
#define MT_MAX    (PADTOT / BM)           // 132
#define KTILES    32                      // 2048 / 64 fp16
#define WD_BLOCKS (MT_MAX * NE)           // 528 Wd-cvt blocks

// ---------------------------------------------------------------------------
// Device scratch (allocation-free rule: __device__ globals)
// ---------------------------------------------------------------------------
__device__ int    g_count[NE];
__device__ int    g_perm[PADTOT];
__device__ __half hX [(size_t)NT_TOKENS * D_DIM];
__device__ __half hWg[(size_t)NE * F_DIM * D_DIM];
__device__ __half hWu[(size_t)NE * F_DIM * D_DIM];
__device__ __half hWd[(size_t)NE * D_DIM * F_DIM];
__device__ __half hH [(size_t)PADTOT * F_DIM];

// ---------------------------------------------------------------------------
// Helpers
// ---------------------------------------------------------------------------
__device__ __forceinline__ int expert_of_i32(int t) {
    if (t < 0) t = 0;
    if (t > VOCAB_SZ - 1) t = VOCAB_SZ - 1;
    int e = t / TPE;
    return e > NE - 1 ? NE - 1 : e;
}

// Per-block dtype detect: token_ids declared int64 but may physically be
// int32 (JAX x64 disabled). If int64 (ids < 2^31), every high word is 0.
// Requires blockDim.x == 256.
__device__ __forceinline__ int detect_shift(const int* __restrict__ tok32,
                                            int* smem_flag) {
    if (threadIdx.x == 0) *smem_flag = 0;
    __syncthreads();
    if (tok32[2 * threadIdx.x + 1] != 0) *smem_flag = 1;
    __syncthreads();
    return *smem_flag ? 0 : 1;
}

// ---------------------------------------------------------------------------
// Kernel 1: fp32->fp16 conversion of X, Wg, Wu  +  routing fused as ONE block.
// grid = (16384, 3):
//   y=0            : X
//   y=1, x<8192    : Wg
//   y=1, x==8192   : routing block (count -> scan -> perm)
//   y=2, x<8192    : Wu
// Wd conversion happens inside k_mlp<0> (overlapped with the gate+up GEMM).
// ---------------------------------------------------------------------------
__global__ void k_cvt_route(const float* __restrict__ X, const float* __restrict__ Wg,
                            const float* __restrict__ Wu, const int* __restrict__ tok32) {
    const int nW = NE * F_DIM * D_DIM;

    if (blockIdx.y == 1 && blockIdx.x == 8192) {
        // ---- routing: single block, 256 threads ----
        __shared__ int flag;
        __shared__ int hist[NE], fill[NE], poff[NE];
        const int shift = detect_shift(tok32, &flag);
        const int tid = threadIdx.x;
        if (tid < NE) { hist[tid] = 0; fill[tid] = 0; }
        __syncthreads();
        for (int k = tid; k < NT_TOKENS; k += 256)
            atomicAdd(&hist[expert_of_i32(tok32[(size_t)k << shift])], 1);
        __syncthreads();
        if (tid == 0) {
            int acc = 0;
#pragma unroll
            for (int e = 0; e < NE; ++e) {
                poff[e] = acc;
                g_count[e] = hist[e];
                acc += (hist[e] + BM - 1) / BM * BM;
            }
        }
        __syncthreads();
        for (int k = tid; k < NT_TOKENS; k += 256) {
            int e = expert_of_i32(tok32[(size_t)k << shift]);
            g_perm[poff[e] + atomicAdd(&fill[e], 1)] = k;
        }
        return;
    }

    const float* src;
    __half* dst;
    int n;
    switch (blockIdx.y) {
        case 0:  src = X;  dst = hX;  n = NT_TOKENS * D_DIM; break;
        case 1:  src = Wg; dst = hWg; n = nW; break;
        default: src = Wu; dst = hWu; n = nW; break;
    }
    int i = (blockIdx.x * blockDim.x + threadIdx.x) * 8;
    if (i < n) {
        float4 f0 = *(const float4*)(src + i);
        float4 f1 = *(const float4*)(src + i + 4);
        __half2 h[4];
        h[0] = __floats2half2_rn(f0.x, f0.y);
        h[1] = __floats2half2_rn(f0.z, f0.w);
        h[2] = __floats2half2_rn(f1.x, f1.y);
        h[3] = __floats2half2_rn(f1.z, f1.w);
        *(uint4*)(dst + i) = *(uint4*)h;
    }
}

// ---------------------------------------------------------------------------
// PTX helpers (sm_100-baseline legal)
// ---------------------------------------------------------------------------
__device__ __forceinline__ void cpa16(uint32_t s, const void* g) {
    asm volatile("cp.async.cg.shared.global [%0], [%1], 16;" :: "r"(s), "l"(g));
}
__device__ __forceinline__ void cpa_commit() {
    asm volatile("cp.async.commit_group;");
}
template <int N> __device__ __forceinline__ void cpa_wait() {
    asm volatile("cp.async.wait_group %0;" :: "n"(N) : "memory");
}
__device__ __forceinline__ void ldm_x4(uint32_t* r, uint32_t addr) {
    asm volatile("ldmatrix.sync.aligned.m8n8.x4.shared.b16 {%0,%1,%2,%3}, [%4];"
                 : "=r"(r[0]), "=r"(r[1]), "=r"(r[2]), "=r"(r[3]) : "r"(addr));
}
__device__ __forceinline__ void mma16816(float* c, const uint32_t* a,
                                         uint32_t b0, uint32_t b1) {
    asm volatile(
        "mma.sync.aligned.m16n8k16.row.col.f32.f16.f16.f32 "
        "{%0,%1,%2,%3}, {%4,%5,%6,%7}, {%8,%9}, {%0,%1,%2,%3};"
        : "+f"(c[0]), "+f"(c[1]), "+f"(c[2]), "+f"(c[3])
        : "r"(a[0]), "r"(a[1]), "r"(a[2]), "r"(a[3]), "r"(b0), "r"(b1));
}

// ---------------------------------------------------------------------------
// MODE 0 (gate+up fused): CTA tile 128x64, 8 warps 4m x 2n.
//   Extra blocks (blockIdx.x == 32) convert Wd fp32->fp16 concurrently.
// MODE 1 (down+scatter):  CTA tile 128x128, 8 warps 4m x 2n (warp 32x64).
// Both: BK=64 fp16, 3-stage cp.async ring (32KB/stage), SW128 XOR swizzle,
// one __syncthreads per k-tile, 2 CTAs/SM, XOR-folded ldmatrix addressing.
//
// Round-14 changes: per-thread offset arrays strength-reduced to base +
// constant stride (valid because the t-stride of 32 rows keeps row&7, hence
// the swizzle term, invariant); prefetch LOADST split into A-half (after
// KSTEP 0) and B-half + commit (after KSTEP 1) to spread LSU issue.
// ---------------------------------------------------------------------------
template <int MODE>
__global__ __launch_bounds__(256, 2)
void k_mlp(float* __restrict__ out, const float* __restrict__ Wd32) {
    constexpr int BN = (MODE == 0) ? 64 : 128;

    if (MODE == 0 && blockIdx.x == F_DIM / 64) {
        // ---- Wd fp32->fp16 conversion (grid-stride over 528 blocks) ----
        const int bid = blockIdx.y * NE + blockIdx.z;          // 0..527
        const size_t stride = (size_t)WD_BLOCKS * 256 * 8;
        for (size_t i = ((size_t)bid * 256 + threadIdx.x) * 8;
             i < (size_t)NE * D_DIM * F_DIM; i += stride) {
            float4 f0 = *(const float4*)(Wd32 + i);
            float4 f1 = *(const float4*)(Wd32 + i + 4);
            __half2 h[4];
            h[0] = __floats2half2_rn(f0.x, f0.y);
            h[1] = __floats2half2_rn(f0.z, f0.w);
            h[2] = __floats2half2_rn(f1.x, f1.y);
            h[3] = __floats2half2_rn(f1.z, f1.w);
            *(uint4*)(hWd + i) = *(uint4*)h;
        }
        return;
    }

    const int e   = blockIdx.z;
    const int cnt = g_count[e];
    const int my  = blockIdx.y;
    if (my * BM >= cnt) return;
    const int n0 = blockIdx.x * BN;

    int base = 0;
#pragma unroll
    for (int k = 0; k < NE; ++k)
        if (k < e) base += (g_count[k] + BM - 1) / BM * BM;
    const int rowstart = base + my * BM;

    constexpr int STAGE = 32768;   // MODE0: A16K+Bg8K+Bu8K ; MODE1: A16K+B16K

    extern __shared__ __align__(16) char smem[];
    const uint32_t su = (uint32_t)__cvta_generic_to_shared(smem);

    const int tid = threadIdx.x;
    const int l   = tid & 31;
    const int wid = tid >> 5;
    const int wm  = (wid & 3) * 32;
    const int wn  = (wid >> 2) * (BN / 2);

    const int c = tid & 7;                             // 16B chunk in 128B row
    const char* const baseA = (MODE == 0) ? (const char*)hX : (const char*)hH;
    const char* const baseB1 = (MODE == 0) ? (const char*)hWg : (const char*)hWd;
    const char* const baseB2 = (const char*)hWu;       // MODE0 only

    // Strength-reduced staging offsets.  row(t) = r0 + 32t; 32 ≡ 0 (mod 8)
    // so the swizzle term (c ^ (row&7)) is t-invariant:
    //   dstA(t) = dstA0 + t*4096,  contiguous-row sources: off(t) = off0 + t*131072.
    const int r0 = tid >> 3;
    const uint32_t dstA0 = (uint32_t)(r0 * 128 + ((c ^ (r0 & 7)) * 16));

    uint32_t aOff[4];                                  // MODE0: gathered rows
    uint32_t aOff0;                                    // MODE1: contiguous
    if (MODE == 0) {
#pragma unroll
        for (int t = 0; t < 4; ++t) {
            const int row = r0 + t * 32;
            const int grow = (my * BM + row) < cnt ? g_perm[rowstart + row] : 0;
            aOff[t] = (uint32_t)grow * (D_DIM * 2) + c * 16;
        }
        aOff0 = 0;
    } else {
        aOff0 = (uint32_t)(rowstart + r0) * (F_DIM * 2) + c * 16;
    }
    const uint32_t bOff0 = (uint32_t)((size_t)e * F_DIM * D_DIM * 2) +
                           (uint32_t)(n0 + r0) * (D_DIM * 2) + c * 16;

    constexpr int NBCHUNK = (MODE == 0) ? 2 : 4;

#define LOADST_A(slot, kt)                                                   \
    do {                                                                     \
        const uint32_t sb = su + (uint32_t)(slot) * STAGE;                   \
        const uint32_t ko = (uint32_t)(kt) * 128;                            \
        _Pragma("unroll")                                                    \
        for (int t = 0; t < 4; ++t)                                          \
            cpa16(sb + dstA0 + t * 4096,                                     \
                  MODE == 0 ? baseA + aOff[t] + ko                           \
                            : baseA + aOff0 + t * 131072 + ko);              \
    } while (0)

#define LOADST_B(slot, kt)                                                   \
    do {                                                                     \
        const uint32_t sb = su + (uint32_t)(slot) * STAGE;                   \
        const uint32_t ko = (uint32_t)(kt) * 128;                            \
        _Pragma("unroll")                                                    \
        for (int t = 0; t < NBCHUNK; ++t) {                                  \
            cpa16(sb + 16384 + dstA0 + t * 4096,                             \
                  baseB1 + bOff0 + t * 131072 + ko);                         \
            if (MODE == 0)                                                   \
                cpa16(sb + 24576 + dstA0 + t * 4096,                         \
                      baseB2 + bOff0 + t * 131072 + ko);                     \
        }                                                                    \
        cpa_commit();                                                        \
    } while (0)

    // ---- precomputed ldmatrix fragment constants ----
    const int kha = (l >> 4) & 1;
    const int khb = (l >> 3) & 1;
    uint32_t pA[2];
#pragma unroll
    for (int mi = 0; mi < 2; ++mi) {
        const int r = wm + mi * 16 + (l & 15);
        pA[mi] = (uint32_t)(r * 128 + ((kha ^ (r & 7)) << 4));
    }
    constexpr int NBF = BN / 32;
    uint32_t pB[NBF];
#pragma unroll
    for (int bi = 0; bi < NBF; ++bi) {
        const int r = wn + bi * 16 + ((l & 16) ? 8 : 0) + (l & 7);
        pB[bi] = (uint32_t)(16384 + r * 128 + ((khb ^ (r & 7)) << 4));
    }

    // ---- accumulators ----
    constexpr int NT = BN / 16;
    float c1[2][NT][4];
    float c2[2][NT][4];                                // MODE0 only
#pragma unroll
    for (int mi = 0; mi < 2; ++mi)
#pragma unroll
        for (int nt = 0; nt < NT; ++nt)
#pragma unroll
            for (int k = 0; k < 4; ++k) { c1[mi][nt][k] = 0.f; if (MODE == 0) c2[mi][nt][k] = 0.f; }

    LOADST_A(0, 0); LOADST_B(0, 0);
    LOADST_A(1, 1); LOADST_B(1, 1);

#define KSTEP(ks)                                                            \
    do {                                                                     \
        const uint32_t kx = (uint32_t)((ks) << 5);                           \
        uint32_t a[2][4];                                                    \
        _Pragma("unroll")                                                    \
        for (int mi = 0; mi < 2; ++mi) ldm_x4(a[mi], sbase + (pA[mi] ^ kx)); \
        uint32_t b1[NBF][4];                                                 \
        _Pragma("unroll")                                                    \
        for (int bi = 0; bi < NBF; ++bi) ldm_x4(b1[bi], sbase + (pB[bi] ^ kx));\
        _Pragma("unroll")                                                    \
        for (int mi = 0; mi < 2; ++mi)                                       \
            _Pragma("unroll")                                                \
            for (int nt = 0; nt < NT; ++nt)                                  \
                mma16816(c1[mi][nt], a[mi], b1[nt >> 1][(nt & 1) * 2],       \
                         b1[nt >> 1][(nt & 1) * 2 + 1]);                     \
        if (MODE == 0) {                                                     \
            uint32_t b2[NBF][4];                                             \
            _Pragma("unroll")                                                \
            for (int bi = 0; bi < NBF; ++bi)                                 \
                ldm_x4(b2[bi], sbase + 8192 + (pB[bi] ^ kx));                \
            _Pragma("unroll")                                                \
            for (int mi = 0; mi < 2; ++mi)                                   \
                _Pragma("unroll")                                            \
                for (int nt = 0; nt < NT; ++nt)                              \
                    mma16816(c2[mi][nt], a[mi], b2[nt >> 1][(nt & 1) * 2],   \
                             b2[nt >> 1][(nt & 1) * 2 + 1]);                 \
        }                                                                    \
    } while (0)

    // Single-sync ring: prefetch for slot (kt+2)%3 == (kt-1)%3 whose readers
    // all finished before this iteration's barrier; reads of slot kt%3 are
    // published block-wide by the same barrier.  A-half of the prefetch goes
    // after KSTEP(0), B-half + commit after KSTEP(1) (LSU issue spread).
    for (int kt = 0; kt < KTILES; ++kt) {
        if (kt == KTILES - 1) cpa_wait<0>(); else cpa_wait<1>();
        __syncthreads();
        const uint32_t sbase = su + (uint32_t)(kt % 3) * STAGE;
        const bool pf = (kt + 2 < KTILES);

        KSTEP(0);
        if (pf) LOADST_A((kt + 2) % 3, kt + 2);
        KSTEP(1);
        if (pf) LOADST_B((kt + 2) % 3, kt + 2);
        KSTEP(2);
        KSTEP(3);
    }
#undef KSTEP
#undef LOADST_A
#undef LOADST_B

    // ---- epilogue ----
    const int g   = l >> 2;
    const int tig = l & 3;
    const int colbase = n0 + wn + tig * 2;

#pragma unroll
    for (int mi = 0; mi < 2; ++mi) {
#pragma unroll
        for (int h = 0; h < 2; ++h) {
            const int row_local = wm + mi * 16 + h * 8 + g;
            const int p = rowstart + row_local;
            if (MODE == 0) {
                __half* dst = hH + (size_t)p * F_DIM + colbase;
#pragma unroll
                for (int nt = 0; nt < NT; ++nt) {
                    float gv0 = c1[mi][nt][h * 2],     uv0 = c2[mi][nt][h * 2];
                    float gv1 = c1[mi][nt][h * 2 + 1], uv1 = c2[mi][nt][h * 2 + 1];
                    float v0 = (gv0 / (1.0f + __expf(-gv0))) * uv0;
                    float v1 = (gv1 / (1.0f + __expf(-gv1))) * uv1;
                    *(__half2*)(dst + nt * 8) = __floats2half2_rn(v0, v1);
                }
            } else {
                if ((my * BM + row_local) < cnt) {
                    const int tok = g_perm[p];
                    float* dst = out + (size_t)tok * D_DIM + colbase;
#pragma unroll
                    for (int nt = 0; nt < NT; ++nt)
                        *(float2*)(dst + nt * 8) =
                            make_float2(c1[mi][nt][h * 2], c1[mi][nt][h * 2 + 1]);
                }
            }
        }
    }
}

// ---------------------------------------------------------------------------
// Entry.  3 launches: cvt+route, gate+up(+Wd cvt), down+scatter.
// ---------------------------------------------------------------------------
extern "C" void kernel_launch(void* const* d_in, const int* in_sizes, int n_in,
                              void* d_out, int out_size) {
    const float* X     = (const float*)d_in[0];
    const int*   tok32 = (const int*)d_in[1];
    const float* Wg    = (const float*)d_in[2];
    const float* Wu    = (const float*)d_in[3];
    const float* Wd    = (const float*)d_in[4];
    float*       out   = (float*)d_out;

    static bool attr_done = false;
    if (!attr_done) {
        cudaFuncSetAttribute(k_mlp<0>, cudaFuncAttributeMaxDynamicSharedMemorySize, 3 * 32768);
        cudaFuncSetAttribute(k_mlp<1>, cudaFuncAttributeMaxDynamicSharedMemorySize, 3 * 32768);
        attr_done = true;
    }

    // 1: conversion of X/Wg/Wu + fused routing block
    dim3 gcvt(NT_TOKENS * D_DIM / (256 * 8), 3);   // (16384, 3)
    k_cvt_route<<<gcvt, 256>>>(X, Wg, Wu, tok32);

    // 2: gate+up GEMM (CTA 128x64) + concurrent Wd conversion blocks
    dim3 grid0(F_DIM / 64 + 1, MT_MAX, NE);        // (33, 132, 4)
    k_mlp<0><<<grid0, 256, 3 * 32768>>>(nullptr, Wd);

    // 3: down GEMM + fused scatter (CTA 128x128)
    dim3 grid1(D_DIM / 128, MT_MAX, NE);           // (16, 132, 4)
    k_mlp<1><<<grid1, 256, 3 * 32768>>>(out, nullptr);
}

// round 16
// speedup vs baseline: 1.0120x; 1.0080x over previous
#include <cuda_runtime.h>
#include <cuda_fp16.h>
#include <cstdint>

// ---------------------------------------------------------------------------
// Problem constants
// ---------------------------------------------------------------------------
#define NT_TOKENS 16384
#define D_DIM     2048
#define F_DIM     2048
#define NE        4
#define VOCAB_SZ  100000
#define TPE       (VOCAB_SZ / NE)

#define BM        128
#define PADTOT    (NT_TOKENS + NE * BM)   // 16896
#define MT_MAX    (PADTOT / BM)           // 132 total padded m-tiles (all experts)
#define KTILES    32                      // 2048 / 64 fp16
#define WD_BLOCKS MT_MAX                  // 132 Wd-cvt blocks

// ---------------------------------------------------------------------------
// Device scratch (allocation-free rule: __device__ globals)
// ---------------------------------------------------------------------------
__device__ int    g_count[NE];
__device__ int    g_perm[PADTOT];
__device__ __half hX [(size_t)NT_TOKENS * D_DIM];
__device__ __half hWg[(size_t)NE * F_DIM * D_DIM];
__device__ __half hWu[(size_t)NE * F_DIM * D_DIM];
__device__ __half hWd[(size_t)NE * D_DIM * F_DIM];
__device__ __half hH [(size_t)PADTOT * F_DIM];

// ---------------------------------------------------------------------------
// Helpers
// ---------------------------------------------------------------------------
__device__ __forceinline__ int expert_of_i32(int t) {
    if (t < 0) t = 0;
    if (t > VOCAB_SZ - 1) t = VOCAB_SZ - 1;
    int e = t / TPE;
    return e > NE - 1 ? NE - 1 : e;
}

// Per-block dtype detect: token_ids declared int64 but may physically be
// int32 (JAX x64 disabled). If int64 (ids < 2^31), every high word is 0.
// Requires blockDim.x == 256.
__device__ __forceinline__ int detect_shift(const int* __restrict__ tok32,
                                            int* smem_flag) {
    if (threadIdx.x == 0) *smem_flag = 0;
    __syncthreads();
    if (tok32[2 * threadIdx.x + 1] != 0) *smem_flag = 1;
    __syncthreads();
    return *smem_flag ? 0 : 1;
}

// Padded-tile-prefix expert lookup.  Because every expert region is padded to
// a BM multiple, padded tile t (0..131) starts at row t*BM, and the owning
// expert is the one whose cumulative padded-tile count exceeds t.
// Returns -1 if t is beyond the last real tile.
__device__ __forceinline__ int expert_of_tile(int t, int* my_local) {
    int cum = 0;
#pragma unroll
    for (int e = 0; e < NE; ++e) {
        const int tiles = (g_count[e] + BM - 1) / BM;
        if (t < cum + tiles) { *my_local = t - cum; return e; }
        cum += tiles;
    }
    return -1;
}

// ---------------------------------------------------------------------------
// Kernel 1: fp32->fp16 conversion of X, Wg, Wu  +  routing fused as ONE block.
// grid = (16384, 3):
//   y=0            : X
//   y=1, x<8192    : Wg
//   y=1, x==8192   : routing block (count -> scan -> perm)
//   y=2, x<8192    : Wu
// Wd conversion happens inside k_mlp<0> (overlapped with the gate+up GEMM).
// ---------------------------------------------------------------------------
__global__ void k_cvt_route(const float* __restrict__ X, const float* __restrict__ Wg,
                            const float* __restrict__ Wu, const int* __restrict__ tok32) {
    const int nW = NE * F_DIM * D_DIM;

    if (blockIdx.y == 1 && blockIdx.x == 8192) {
        // ---- routing: single block, 256 threads ----
        __shared__ int flag;
        __shared__ int hist[NE], fill[NE], poff[NE];
        const int shift = detect_shift(tok32, &flag);
        const int tid = threadIdx.x;
        if (tid < NE) { hist[tid] = 0; fill[tid] = 0; }
        __syncthreads();
        for (int k = tid; k < NT_TOKENS; k += 256)
            atomicAdd(&hist[expert_of_i32(tok32[(size_t)k << shift])], 1);
        __syncthreads();
        if (tid == 0) {
            int acc = 0;
#pragma unroll
            for (int e = 0; e < NE; ++e) {
                poff[e] = acc;
                g_count[e] = hist[e];
                acc += (hist[e] + BM - 1) / BM * BM;
            }
        }
        __syncthreads();
        for (int k = tid; k < NT_TOKENS; k += 256) {
            int e = expert_of_i32(tok32[(size_t)k << shift]);
            g_perm[poff[e] + atomicAdd(&fill[e], 1)] = k;
        }
        return;
    }

    const float* src;
    __half* dst;
    int n;
    switch (blockIdx.y) {
        case 0:  src = X;  dst = hX;  n = NT_TOKENS * D_DIM; break;
        case 1:  src = Wg; dst = hWg; n = nW; break;
        default: src = Wu; dst = hWu; n = nW; break;
    }
    int i = (blockIdx.x * blockDim.x + threadIdx.x) * 8;
    if (i < n) {
        float4 f0 = *(const float4*)(src + i);
        float4 f1 = *(const float4*)(src + i + 4);
        __half2 h[4];
        h[0] = __floats2half2_rn(f0.x, f0.y);
        h[1] = __floats2half2_rn(f0.z, f0.w);
        h[2] = __floats2half2_rn(f1.x, f1.y);
        h[3] = __floats2half2_rn(f1.z, f1.w);
        *(uint4*)(dst + i) = *(uint4*)h;
    }
}

// ---------------------------------------------------------------------------
// PTX helpers (sm_100-baseline legal)
// ---------------------------------------------------------------------------
__device__ __forceinline__ void cpa16(uint32_t s, const void* g) {
    asm volatile("cp.async.cg.shared.global [%0], [%1], 16;" :: "r"(s), "l"(g));
}
__device__ __forceinline__ void cpa_commit() {
    asm volatile("cp.async.commit_group;");
}
template <int N> __device__ __forceinline__ void cpa_wait() {
    asm volatile("cp.async.wait_group %0;" :: "n"(N) : "memory");
}
__device__ __forceinline__ void ldm_x4(uint32_t* r, uint32_t addr) {
    asm volatile("ldmatrix.sync.aligned.m8n8.x4.shared.b16 {%0,%1,%2,%3}, [%4];"
                 : "=r"(r[0]), "=r"(r[1]), "=r"(r[2]), "=r"(r[3]) : "r"(addr));
}
__device__ __forceinline__ void mma16816(float* c, const uint32_t* a,
                                         uint32_t b0, uint32_t b1) {
    asm volatile(
        "mma.sync.aligned.m16n8k16.row.col.f32.f16.f16.f32 "
        "{%0,%1,%2,%3}, {%4,%5,%6,%7}, {%8,%9}, {%0,%1,%2,%3};"
        : "+f"(c[0]), "+f"(c[1]), "+f"(c[2]), "+f"(c[3])
        : "r"(a[0]), "r"(a[1]), "r"(a[2]), "r"(a[3]), "r"(b0), "r"(b1));
}

// ---------------------------------------------------------------------------
// MODE 0 (gate+up fused): CTA tile 128x64, 8 warps 4m x 2n.
// MODE 1 (down+scatter):  CTA tile 128x128, 8 warps 4m x 2n (warp 32x64).
// Both: BK=64 fp16, 3-stage cp.async ring (32KB/stage), SW128 XOR swizzle,
// one __syncthreads per k-tile, 2 CTAs/SM, XOR-folded ldmatrix addressing,
// strength-reduced staging offsets, split A/B prefetch.
//
// Flattened grids: the y dimension covers TOTAL padded m-tiles (<=132),
// eliminating ~19k empty per-expert CTAs.  rowstart == tile*BM by the
// BM-alignment identity; the expert is found via a 4-entry prefix compare.
// ---------------------------------------------------------------------------
template <int MODE>
__device__ __forceinline__ void gemm_body(int e, int my_local, int rowstart,
                                          int n0, float* __restrict__ out) {
    constexpr int BN = (MODE == 0) ? 64 : 128;
    const int cnt = g_count[e];

    constexpr int STAGE = 32768;   // MODE0: A16K+Bg8K+Bu8K ; MODE1: A16K+B16K

    extern __shared__ __align__(16) char smem[];
    const uint32_t su = (uint32_t)__cvta_generic_to_shared(smem);

    const int tid = threadIdx.x;
    const int l   = tid & 31;
    const int wid = tid >> 5;
    const int wm  = (wid & 3) * 32;
    const int wn  = (wid >> 2) * (BN / 2);

    const int c = tid & 7;                             // 16B chunk in 128B row
    const char* const baseA = (MODE == 0) ? (const char*)hX : (const char*)hH;
    const char* const baseB1 = (MODE == 0) ? (const char*)hWg : (const char*)hWd;
    const char* const baseB2 = (const char*)hWu;       // MODE0 only

    // Strength-reduced staging offsets.  row(t) = r0 + 32t; 32 ≡ 0 (mod 8)
    // keeps the swizzle term (c ^ (row&7)) t-invariant.
    const int r0 = tid >> 3;
    const uint32_t dstA0 = (uint32_t)(r0 * 128 + ((c ^ (r0 & 7)) * 16));

    uint32_t aOff[4];                                  // MODE0: gathered rows
    uint32_t aOff0;                                    // MODE1: contiguous
    if (MODE == 0) {
#pragma unroll
        for (int t = 0; t < 4; ++t) {
            const int row = r0 + t * 32;
            const int grow = (my_local * BM + row) < cnt ? g_perm[rowstart + row] : 0;
            aOff[t] = (uint32_t)grow * (D_DIM * 2) + c * 16;
        }
        aOff0 = 0;
    } else {
        aOff0 = (uint32_t)(rowstart + r0) * (F_DIM * 2) + c * 16;
    }
    const uint32_t bOff0 = (uint32_t)((size_t)e * F_DIM * D_DIM * 2) +
                           (uint32_t)(n0 + r0) * (D_DIM * 2) + c * 16;

    constexpr int NBCHUNK = (MODE == 0) ? 2 : 4;

#define LOADST_A(slot, kt)                                                   \
    do {                                                                     \
        const uint32_t sb = su + (uint32_t)(slot) * STAGE;                   \
        const uint32_t ko = (uint32_t)(kt) * 128;                            \
        _Pragma("unroll")                                                    \
        for (int t = 0; t < 4; ++t)                                          \
            cpa16(sb + dstA0 + t * 4096,                                     \
                  MODE == 0 ? baseA + aOff[t] + ko                           \
                            : baseA + aOff0 + t * 131072 + ko);              \
    } while (0)

#define LOADST_B(slot, kt)                                                   \
    do {                                                                     \
        const uint32_t sb = su + (uint32_t)(slot) * STAGE;                   \
        const uint32_t ko = (uint32_t)(kt) * 128;                            \
        _Pragma("unroll")                                                    \
        for (int t = 0; t < NBCHUNK; ++t) {                                  \
            cpa16(sb + 16384 + dstA0 + t * 4096,                             \
                  baseB1 + bOff0 + t * 131072 + ko);                         \
            if (MODE == 0)                                                   \
                cpa16(sb + 24576 + dstA0 + t * 4096,                         \
                      baseB2 + bOff0 + t * 131072 + ko);                     \
        }                                                                    \
        cpa_commit();                                                        \
    } while (0)

    // ---- precomputed ldmatrix fragment constants ----
    const int kha = (l >> 4) & 1;
    const int khb = (l >> 3) & 1;
    uint32_t pA[2];
#pragma unroll
    for (int mi = 0; mi < 2; ++mi) {
        const int r = wm + mi * 16 + (l & 15);
        pA[mi] = (uint32_t)(r * 128 + ((kha ^ (r & 7)) << 4));
    }
    constexpr int NBF = BN / 32;
    uint32_t pB[NBF];
#pragma unroll
    for (int bi = 0; bi < NBF; ++bi) {
        const int r = wn + bi * 16 + ((l & 16) ? 8 : 0) + (l & 7);
        pB[bi] = (uint32_t)(16384 + r * 128 + ((khb ^ (r & 7)) << 4));
    }

    // ---- accumulators ----
    constexpr int NT = BN / 16;
    float c1[2][NT][4];
    float c2[2][NT][4];                                // MODE0 only
#pragma unroll
    for (int mi = 0; mi < 2; ++mi)
#pragma unroll
        for (int nt = 0; nt < NT; ++nt)
#pragma unroll
            for (int k = 0; k < 4; ++k) { c1[mi][nt][k] = 0.f; if (MODE == 0) c2[mi][nt][k] = 0.f; }

    LOADST_A(0, 0); LOADST_B(0, 0);
    LOADST_A(1, 1); LOADST_B(1, 1);

#define KSTEP(ks)                                                            \
    do {                                                                     \
        const uint32_t kx = (uint32_t)((ks) << 5);                           \
        uint32_t a[2][4];                                                    \
        _Pragma("unroll")                                                    \
        for (int mi = 0; mi < 2; ++mi) ldm_x4(a[mi], sbase + (pA[mi] ^ kx)); \
        uint32_t b1[NBF][4];                                                 \
        _Pragma("unroll")                                                    \
        for (int bi = 0; bi < NBF; ++bi) ldm_x4(b1[bi], sbase + (pB[bi] ^ kx));\
        _Pragma("unroll")                                                    \
        for (int mi = 0; mi < 2; ++mi)                                       \
            _Pragma("unroll")                                                \
            for (int nt = 0; nt < NT; ++nt)                                  \
                mma16816(c1[mi][nt], a[mi], b1[nt >> 1][(nt & 1) * 2],       \
                         b1[nt >> 1][(nt & 1) * 2 + 1]);                     \
        if (MODE == 0) {                                                     \
            uint32_t b2[NBF][4];                                             \
            _Pragma("unroll")                                                \
            for (int bi = 0; bi < NBF; ++bi)                                 \
                ldm_x4(b2[bi], sbase + 8192 + (pB[bi] ^ kx));                \
            _Pragma("unroll")                                                \
            for (int mi = 0; mi < 2; ++mi)                                   \
                _Pragma("unroll")                                            \
                for (int nt = 0; nt < NT; ++nt)                              \
                    mma16816(c2[mi][nt], a[mi], b2[nt >> 1][(nt & 1) * 2],   \
                             b2[nt >> 1][(nt & 1) * 2 + 1]);                 \
        }                                                                    \
    } while (0)

    // Single-sync ring: prefetch for slot (kt+2)%3 == (kt-1)%3 whose readers
    // all finished before this iteration's barrier; reads of slot kt%3 are
    // published block-wide by the same barrier.  A-half of the prefetch goes
    // after KSTEP(0), B-half + commit after KSTEP(1).
    for (int kt = 0; kt < KTILES; ++kt) {
        if (kt == KTILES - 1) cpa_wait<0>(); else cpa_wait<1>();
        __syncthreads();
        const uint32_t sbase = su + (uint32_t)(kt % 3) * STAGE;
        const bool pf = (kt + 2 < KTILES);

        KSTEP(0);
        if (pf) LOADST_A((kt + 2) % 3, kt + 2);
        KSTEP(1);
        if (pf) LOADST_B((kt + 2) % 3, kt + 2);
        KSTEP(2);
        KSTEP(3);
    }
#undef KSTEP
#undef LOADST_A
#undef LOADST_B

    // ---- epilogue ----
    const int g   = l >> 2;
    const int tig = l & 3;
    const int colbase = n0 + wn + tig * 2;

#pragma unroll
    for (int mi = 0; mi < 2; ++mi) {
#pragma unroll
        for (int h = 0; h < 2; ++h) {
            const int row_local = wm + mi * 16 + h * 8 + g;
            const int p = rowstart + row_local;
            if (MODE == 0) {
                __half* dst = hH + (size_t)p * F_DIM + colbase;
#pragma unroll
                for (int nt = 0; nt < NT; ++nt) {
                    float gv0 = c1[mi][nt][h * 2],     uv0 = c2[mi][nt][h * 2];
                    float gv1 = c1[mi][nt][h * 2 + 1], uv1 = c2[mi][nt][h * 2 + 1];
                    float v0 = (gv0 / (1.0f + __expf(-gv0))) * uv0;
                    float v1 = (gv1 / (1.0f + __expf(-gv1))) * uv1;
                    *(__half2*)(dst + nt * 8) = __floats2half2_rn(v0, v1);
                }
            } else {
                if ((my_local * BM + row_local) < cnt) {
                    const int tok = g_perm[p];
                    float* dst = out + (size_t)tok * D_DIM + colbase;
#pragma unroll
                    for (int nt = 0; nt < NT; ++nt)
                        *(float2*)(dst + nt * 8) =
                            make_float2(c1[mi][nt][h * 2], c1[mi][nt][h * 2 + 1]);
                }
            }
        }
    }
}

// ---------------------------------------------------------------------------
// GEMM kernels with flattened grids.
// MODE 0: grid (33, 132, 1).  x<32: gate+up tile (n0=x*64);  x==32: Wd cvt.
// MODE 1: grid (16, 132, 1).  down+scatter tile (n0=x*128).
// ---------------------------------------------------------------------------
template <int MODE>
__global__ __launch_bounds__(256, 2)
void k_mlp(float* __restrict__ out, const float* __restrict__ Wd32) {
    if (MODE == 0 && blockIdx.x == F_DIM / 64) {
        // ---- Wd fp32->fp16 conversion (grid-stride over 132 blocks) ----
        const int bid = blockIdx.y;                    // 0..131
        const size_t stride = (size_t)WD_BLOCKS * 256 * 8;
        for (size_t i = ((size_t)bid * 256 + threadIdx.x) * 8;
             i < (size_t)NE * D_DIM * F_DIM; i += stride) {
            float4 f0 = *(const float4*)(Wd32 + i);
            float4 f1 = *(const float4*)(Wd32 + i + 4);
            __half2 h[4];
            h[0] = __floats2half2_rn(f0.x, f0.y);
            h[1] = __floats2half2_rn(f0.z, f0.w);
            h[2] = __floats2half2_rn(f1.x, f1.y);
            h[3] = __floats2half2_rn(f1.z, f1.w);
            *(uint4*)(hWd + i) = *(uint4*)h;
        }
        return;
    }

    int my_local;
    const int e = expert_of_tile(blockIdx.y, &my_local);
    if (e < 0) return;                                 // beyond last real tile
    const int rowstart = blockIdx.y * BM;              // BM-alignment identity
    constexpr int BNX = (MODE == 0) ? 64 : 128;
    gemm_body<MODE>(e, my_local, rowstart, blockIdx.x * BNX, out);
}

// ---------------------------------------------------------------------------
// Entry.  3 launches: cvt+route, gate+up(+Wd cvt), down+scatter.
// ---------------------------------------------------------------------------
extern "C" void kernel_launch(void* const* d_in, const int* in_sizes, int n_in,
                              void* d_out, int out_size) {
    const float* X     = (const float*)d_in[0];
    const int*   tok32 = (const int*)d_in[1];
    const float* Wg    = (const float*)d_in[2];
    const float* Wu    = (const float*)d_in[3];
    const float* Wd    = (const float*)d_in[4];
    float*       out   = (float*)d_out;

    static bool attr_done = false;
    if (!attr_done) {
        cudaFuncSetAttribute(k_mlp<0>, cudaFuncAttributeMaxDynamicSharedMemorySize, 3 * 32768);
        cudaFuncSetAttribute(k_mlp<1>, cudaFuncAttributeMaxDynamicSharedMemorySize, 3 * 32768);
        attr_done = true;
    }

    // 1: conversion of X/Wg/Wu + fused routing block
    dim3 gcvt(NT_TOKENS * D_DIM / (256 * 8), 3);   // (16384, 3)
    k_cvt_route<<<gcvt, 256>>>(X, Wg, Wu, tok32);

    // 2: gate+up GEMM over total padded m-tiles + Wd cvt column
    dim3 grid0(F_DIM / 64 + 1, MT_MAX, 1);         // (33, 132)
    k_mlp<0><<<grid0, 256, 3 * 32768>>>(nullptr, Wd);

    // 3: down GEMM + fused scatter over total padded m-tiles
    dim3 grid1(D_DIM / 128, MT_MAX, 1);            // (16, 132)
    k_mlp<1><<<grid1, 256, 3 * 32768>>>(out, nullptr);
}